// round 5
// baseline (speedup 1.0000x reference)
#include <cuda_runtime.h>

// Problem constants
#define NB 8
#define NC 21
#define NW 512
#define NH 512
#define KK 5
#define KPAD 2
#define PLANE (NW * NH)

// Scratch: per-pixel argmax class (labels < 21 fit in u8). Static device
// array -> no allocation inside kernel_launch.
__device__ unsigned char g_xm[NB * PLANE];

// ---------------------------------------------------------------------------
// Kernel A: pure streaming argmax over 21 channels. No smem, no barriers.
// 256 threads, 4 pixels each (float4 loads). Grid = NB*PLANE/1024 = 2048.
// ---------------------------------------------------------------------------
__global__ __launch_bounds__(256)
void argmax_kernel(const float* __restrict__ x, unsigned char* __restrict__ xm)
{
    const int gid = blockIdx.x * 256 + threadIdx.x;
    const int q0  = gid * 4;                 // flat pixel index (b*PLANE + p)
    const int b   = q0 / PLANE;
    const int p   = q0 - b * PLANE;

    const float* xb = x + (size_t)(b * NC) * PLANE + p;   // channel 0
    float4 best = *reinterpret_cast<const float4*>(xb);
    int bc0 = 0, bc1 = 0, bc2 = 0, bc3 = 0;

    #pragma unroll 5
    for (int c = 1; c < NC; c++) {
        const float4 v = *reinterpret_cast<const float4*>(xb + c * PLANE);
        if (v.x > best.x) { best.x = v.x; bc0 = c; }
        if (v.y > best.y) { best.y = v.y; bc1 = c; }
        if (v.z > best.z) { best.z = v.z; bc2 = c; }
        if (v.w > best.w) { best.w = v.w; bc3 = c; }
    }

    uchar4 o;
    o.x = (unsigned char)bc0;
    o.y = (unsigned char)bc1;
    o.z = (unsigned char)bc2;
    o.w = (unsigned char)bc3;
    *reinterpret_cast<uchar4*>(xm + q0) = o;
}

// ---------------------------------------------------------------------------
// Kernel B: 5x5 neighborhood mismatch count vs staged y tile (R1 machinery).
// 128 threads, one row w per block, 4 pixels/thread. Grid (NW, NB).
// ---------------------------------------------------------------------------
__global__ __launch_bounds__(128, 8)
void count_kernel(const int* __restrict__ y,
                  const unsigned char* __restrict__ xm,
                  float* __restrict__ out)
{
    // Row stride 520 ints (2080B, 16B multiple) -> int4 LDS conflict-free.
    __shared__ int ytile[KK][520];

    const int w   = blockIdx.x;
    const int b   = blockIdx.y;
    const int tid = threadIdx.x;
    const int h0  = tid * 4;

    // ---- stage y neighborhood rows into smem (zero padding like Unfold) ----
    const int* yb = y + b * PLANE;
    for (int idx = tid; idx < KK * 516; idx += 128) {
        const int r  = idx / 516;          // 0..4
        const int cc = idx - r * 516;      // 0..515 (stored col)
        const int gr = w - KPAD + r;
        const int gc = cc - KPAD;
        int v = 0;
        if (gr >= 0 && gr < NW && gc >= 0 && gc < NH)
            v = __ldg(&yb[gr * NH + gc]);
        ytile[r][cc] = v;
    }

    // ---- load 4 argmax classes (coalesced uchar4; issued before barrier) ----
    const uchar4 m = *reinterpret_cast<const uchar4*>(xm + b * PLANE + w * NH + h0);
    const int bc0 = m.x, bc1 = m.y, bc2 = m.z, bc3 = m.w;

    __syncthreads();

    // ---- 5x5 mismatch count ----
    int cnt0 = 0, cnt1 = 0, cnt2 = 0, cnt3 = 0;

    #pragma unroll
    for (int di = 0; di < KK; di++) {
        const int4 lo = *reinterpret_cast<const int4*>(&ytile[di][h0]);
        const int4 hi = *reinterpret_cast<const int4*>(&ytile[di][h0 + 4]);
        const int a0 = lo.x, a1 = lo.y, a2 = lo.z, a3 = lo.w;
        const int a4 = hi.x, a5 = hi.y, a6 = hi.z, a7 = hi.w;

        cnt0 += (a0 != bc0) + (a1 != bc0) + (a2 != bc0) + (a3 != bc0) + (a4 != bc0);
        cnt1 += (a1 != bc1) + (a2 != bc1) + (a3 != bc1) + (a4 != bc1) + (a5 != bc1);
        cnt2 += (a2 != bc2) + (a3 != bc2) + (a4 != bc2) + (a5 != bc2) + (a6 != bc2);
        cnt3 += (a3 != bc3) + (a4 != bc3) + (a5 != bc3) + (a6 != bc3) + (a7 != bc3);
    }

    float4 o;
    o.x = 1.0f + 1.5f * (float)cnt0;
    o.y = 1.0f + 1.5f * (float)cnt1;
    o.z = 1.0f + 1.5f * (float)cnt2;
    o.w = 1.0f + 1.5f * (float)cnt3;

    *reinterpret_cast<float4*>(out + (b * NW + w) * NH + h0) = o;
}

extern "C" void kernel_launch(void* const* d_in, const int* in_sizes, int n_in,
                              void* d_out, int out_size)
{
    const float* x = (const float*)d_in[0];
    const int*   y = (const int*)d_in[1];
    float*       o = (float*)d_out;

    unsigned char* xm = nullptr;
    cudaGetSymbolAddress((void**)&xm, g_xm);

    argmax_kernel<<<(NB * PLANE) / 1024, 256>>>(x, xm);

    dim3 grid(NW, NB);
    count_kernel<<<grid, 128>>>(y, xm, o);
}

// round 6
// speedup vs baseline: 1.2227x; 1.2227x over previous
#include <cuda_runtime.h>

// Problem constants
#define NB 8
#define NC 21
#define NW 512
#define NH 512
#define KK 5
#define KPAD 2
#define PLANE (NW * NH)

// 5-lane packing constants (6-bit lanes at bits 0,6,12,18,24; labels < 32)
#define LREP 0x01041041u   // 1 in each lane
#define CADD 0x1F7DF7DFu   // 31 in each lane
#define MBIT 0x20820820u   // bit5 of each lane

// Block: 128 threads, one row w, 4 contiguous h-pixels per thread (float4).
// Grid: (NW, NB).
__global__ __launch_bounds__(128, 10)
void weight_matrix_kernel(const float* __restrict__ x,
                          const int*   __restrict__ y,
                          float*       __restrict__ out)
{
    // spack[i] = labels of rows w-2..w+2 at global col (i-2), packed into
    // 6-bit lanes (row r -> bits 6r). Cols outside [0,512) pack to 0 (Unfold
    // zero padding; lane value 0 then mismatches any class c!=0, matching ref).
    __shared__ unsigned int spack[520];   // 2080 B

    const int w   = blockIdx.x;
    const int b   = blockIdx.y;
    const int tid = threadIdx.x;
    const int h0  = tid * 4;

    // ---- stage packed column words (5 coalesced row reads per entry) ----
    const int* yb = y + b * PLANE;
    for (int i = tid; i < 520; i += 128) {
        const int gc = i - KPAD;
        unsigned int pack = 0;
        if (gc >= 0 && gc < NH) {
            #pragma unroll
            for (int r = 0; r < KK; r++) {
                const int gr = w - KPAD + r;
                unsigned int v = 0;
                if (gr >= 0 && gr < NW) v = (unsigned)__ldg(&yb[gr * NH + gc]);
                pack |= v << (6 * r);
            }
        }
        spack[i] = pack;
    }
    __syncthreads();

    // ---- argmax over 21 channels for 4 pixels (strict > => first index) ----
    const float* xb = x + (size_t)(b * NC) * PLANE + w * NH + h0;
    float4 best = *reinterpret_cast<const float4*>(xb);
    int bc0 = 0, bc1 = 0, bc2 = 0, bc3 = 0;

    #pragma unroll 5
    for (int c = 1; c < NC; c++) {
        const float4 v = *reinterpret_cast<const float4*>(xb + c * PLANE);
        if (v.x > best.x) { best.x = v.x; bc0 = c; }
        if (v.y > best.y) { best.y = v.y; bc1 = c; }
        if (v.z > best.z) { best.z = v.z; bc2 = c; }
        if (v.w > best.w) { best.w = v.w; bc3 = c; }
    }

    // ---- 5x5 mismatch count via packed lanes ----
    // Pixel p (global col h0+p) needs stored cols (h0+p)..(h0+p+4) of spack.
    // Thread window = spack[h0 .. h0+8) : two aligned int4 loads.
    const uint4 lo = *reinterpret_cast<const uint4*>(&spack[h0]);
    const uint4 hi = *reinterpret_cast<const uint4*>(&spack[h0 + 4]);
    const unsigned int w0 = lo.x, w1 = lo.y, w2 = lo.z, w3 = lo.w;
    const unsigned int w4 = hi.x, w5 = hi.y, w6 = hi.z, w7 = hi.w;

    const unsigned int r0 = (unsigned)bc0 * LREP;
    const unsigned int r1 = (unsigned)bc1 * LREP;
    const unsigned int r2 = (unsigned)bc2 * LREP;
    const unsigned int r3 = (unsigned)bc3 * LREP;

    // popc(((word ^ rep) + CADD) & MBIT) = # mismatching rows in that column
    #define CNT(wd, rp) __popc((((wd) ^ (rp)) + CADD) & MBIT)

    const int cnt0 = CNT(w0,r0)+CNT(w1,r0)+CNT(w2,r0)+CNT(w3,r0)+CNT(w4,r0);
    const int cnt1 = CNT(w1,r1)+CNT(w2,r1)+CNT(w3,r1)+CNT(w4,r1)+CNT(w5,r1);
    const int cnt2 = CNT(w2,r2)+CNT(w3,r2)+CNT(w4,r2)+CNT(w5,r2)+CNT(w6,r2);
    const int cnt3 = CNT(w3,r3)+CNT(w4,r3)+CNT(w5,r3)+CNT(w6,r3)+CNT(w7,r3);
    #undef CNT

    float4 o;
    o.x = 1.0f + 1.5f * (float)cnt0;
    o.y = 1.0f + 1.5f * (float)cnt1;
    o.z = 1.0f + 1.5f * (float)cnt2;
    o.w = 1.0f + 1.5f * (float)cnt3;

    *reinterpret_cast<float4*>(out + (b * NW + w) * NH + h0) = o;
}

extern "C" void kernel_launch(void* const* d_in, const int* in_sizes, int n_in,
                              void* d_out, int out_size)
{
    const float* x = (const float*)d_in[0];
    const int*   y = (const int*)d_in[1];
    float*       o = (float*)d_out;

    dim3 grid(NW, NB);
    weight_matrix_kernel<<<grid, 128>>>(x, y, o);
}